// round 7
// baseline (speedup 1.0000x reference)
#include <cuda_runtime.h>

// AutogradLoss, serial two-kernel structure.
//   K1 loss_grad: read x,y (streaming) -> write loss, dloss with EVICT-NORMAL
//                 stores so the 134 MB of dirty lines stay in L2 (126 MB) and
//                 drain during K2's pure-write phase (same bus direction, no
//                 read<->write turnaround tax).
//   K2 hess:      sqd_loss = 2*I per sample, streaming stores (evict-first, so
//                 K2's own lines recycle among themselves and push K1's dirty
//                 lines out as writebacks).
// Output layout: [loss (B*16) | d_loss (B*16) | sqd_loss (B*256)] floats.

__global__ void __launch_bounds__(256) loss_grad_kernel(
        const float4* __restrict__ x,
        const float4* __restrict__ y,
        float4* __restrict__ loss,
        float4* __restrict__ dloss,
        int n4) {
    int base = blockIdx.x * (256 * 4) + threadIdx.x;
    #pragma unroll
    for (int j = 0; j < 4; j++) {
        int idx = base + j * 256;
        if (idx < n4) {
            float4 a = __ldcs(&x[idx]);   // evict-first: don't displace dirty lines
            float4 b = __ldcs(&y[idx]);
            float dx = a.x - b.x, dy = a.y - b.y;
            float dz = a.z - b.z, dw = a.w - b.w;
            // Evict-normal stores: let them sit dirty in L2.
            loss[idx]  = make_float4(dx * dx, dy * dy, dz * dz, dw * dw);
            dloss[idx] = make_float4(2.f * dx, 2.f * dy, 2.f * dz, 2.f * dw);
        }
    }
}

// f4 index i: within-sample f4 pos = i&63; flat offset s0 = pos*4;
// row = s0>>4, col0 = s0&15; element e is 2.0 iff row == col0+e.
__global__ void __launch_bounds__(256) hess_kernel(float4* __restrict__ sq,
                                                   long long n4) {
    long long base = (long long)blockIdx.x * (256 * 8) + threadIdx.x;
    #pragma unroll
    for (int j = 0; j < 8; j++) {
        long long i = base + j * 256;
        if (i < n4) {
            int s0 = ((int)i & 63) << 2;
            int row = s0 >> 4;
            int col0 = s0 & 15;
            float4 v;
            v.x = (row == col0)     ? 2.0f : 0.0f;
            v.y = (row == col0 + 1) ? 2.0f : 0.0f;
            v.z = (row == col0 + 2) ? 2.0f : 0.0f;
            v.w = (row == col0 + 3) ? 2.0f : 0.0f;
            __stcs(&sq[i], v);   // streaming / evict-first
        }
    }
}

extern "C" void kernel_launch(void* const* d_in, const int* in_sizes, int n_in,
                              void* d_out, int out_size) {
    const float* x = (const float*)d_in[0];
    const float* y = (const float*)d_in[1];
    float* out = (float*)d_out;

    long long bd = in_sizes[0];          // B*16 floats
    long long n4_ld = bd / 4;            // float4 for loss / d_loss
    long long n4_sq = bd * 4;            // float4 for sqd_loss (bd*16/4)

    float* loss  = out;
    float* dloss = out + bd;
    float* sq    = out + 2 * bd;

    {
        long long per_block = 256LL * 4;
        int blocks = (int)((n4_ld + per_block - 1) / per_block);
        loss_grad_kernel<<<blocks, 256>>>((const float4*)x, (const float4*)y,
                                          (float4*)loss, (float4*)dloss,
                                          (int)n4_ld);
    }
    {
        long long per_block = 256LL * 8;
        int blocks = (int)((n4_sq + per_block - 1) / per_block);
        hess_kernel<<<blocks, 256>>>((float4*)sq, n4_sq);
    }
}